// round 4
// baseline (speedup 1.0000x reference)
#include <cuda_runtime.h>

#define B_  8
#define T_  2048
#define NH  4
#define HD  32
#define CE  128
#define QKVS 384

// Scratch (device globals: allocation-free, graph-capturable)
__device__ float g_qkv[(size_t)B_ * T_ * QKVS];  // [B,T,384]  q|k|v interleaved
__device__ float g_y[(size_t)B_ * T_ * CE];      // [B,T,128]  attention output

// ---------------------------------------------------------------------------
// GEMM + bias: C[M,N] = A[M,K] @ W[K,N] + bias
// BM=64, BN=128, BK=32, 256 threads, 4x8 micro-tile.
// MODE 0: A = param (x),  C = g_qkv
// MODE 1: A = g_y,        C = param (d_out)
// ---------------------------------------------------------------------------
template <int MODE>
__global__ __launch_bounds__(256) void gemm_bias_kernel(
    const float* __restrict__ Ap, const float* __restrict__ W,
    const float* __restrict__ bias, float* __restrict__ Cp,
    int M, int N, int K)
{
    const float* A  = (MODE == 0) ? Ap : g_y;
    float*       Cm = (MODE == 0) ? g_qkv : Cp;

    __shared__ float As[64 * 36];    // [row][k], pad 36
    __shared__ float Ws[32 * 128];   // [k][n]

    const int tid = threadIdx.x;
    const int ty  = tid >> 4;        // 0..15 -> 4 rows each
    const int tx  = tid & 15;        // 0..15 -> 8 cols each
    const int bm0 = blockIdx.x * 64;
    const int bn0 = blockIdx.y * 128;

    float acc[4][8];
    #pragma unroll
    for (int i = 0; i < 4; i++)
        #pragma unroll
        for (int j = 0; j < 8; j++) acc[i][j] = 0.f;

    for (int k0 = 0; k0 < K; k0 += 32) {
        #pragma unroll
        for (int it = 0; it < 2; it++) {
            int fid = tid + it * 256;
            int r = fid >> 3, k4 = fid & 7;
            float4 v = *(const float4*)(A + (size_t)(bm0 + r) * K + k0 + k4 * 4);
            *(float4*)(As + r * 36 + k4 * 4) = v;
        }
        #pragma unroll
        for (int it = 0; it < 4; it++) {
            int fid = tid + it * 256;
            int kr = fid >> 5, n4 = fid & 31;
            float4 v = *(const float4*)(W + (size_t)(k0 + kr) * N + bn0 + n4 * 4);
            *(float4*)(Ws + kr * 128 + n4 * 4) = v;
        }
        __syncthreads();

        #pragma unroll
        for (int k = 0; k < 32; k++) {
            float aa[4];
            #pragma unroll
            for (int i = 0; i < 4; i++) aa[i] = As[(ty * 4 + i) * 36 + k];
            float4 b0 = *(const float4*)(Ws + k * 128 + tx * 8);
            float4 b1 = *(const float4*)(Ws + k * 128 + tx * 8 + 4);
            float bb[8] = {b0.x, b0.y, b0.z, b0.w, b1.x, b1.y, b1.z, b1.w};
            #pragma unroll
            for (int i = 0; i < 4; i++)
                #pragma unroll
                for (int j = 0; j < 8; j++)
                    acc[i][j] = fmaf(aa[i], bb[j], acc[i][j]);
        }
        __syncthreads();
    }

    float4 bva = *(const float4*)(bias + bn0 + tx * 8);
    float4 bvb = *(const float4*)(bias + bn0 + tx * 8 + 4);
    #pragma unroll
    for (int i = 0; i < 4; i++) {
        int row = bm0 + ty * 4 + i;
        float* cp = Cm + (size_t)row * N + bn0 + tx * 8;
        float4 r0, r1;
        r0.x = acc[i][0] + bva.x; r0.y = acc[i][1] + bva.y;
        r0.z = acc[i][2] + bva.z; r0.w = acc[i][3] + bva.w;
        r1.x = acc[i][4] + bvb.x; r1.y = acc[i][5] + bvb.y;
        r1.z = acc[i][6] + bvb.z; r1.w = acc[i][7] + bvb.w;
        *(float4*)(cp)     = r0;
        *(float4*)(cp + 4) = r1;
    }
}

// ---------------------------------------------------------------------------
// Flash attention (causal, fp32). One CTA per (b, h, 64-query tile).
// 256 threads. BM=64 queries, BN=64 keys/tile, D=32.
// S-GEMM: thread (ty,tx) owns 4x4 of S. Online softmax with half-warp shfl
// reductions (row spread across the 16 tx lanes of a half-warp).
// P staged via smem; PV-GEMM: thread owns 4 rows x 2 dims of O.
// ---------------------------------------------------------------------------
__global__ __launch_bounds__(256) void attn_kernel()
{
    __shared__ float Qt[32 * 68];   // [d][row]  transposed, pad 68
    __shared__ float Kt[32 * 68];   // [d][col]
    __shared__ float Vs[64 * 32];   // [col][d]
    __shared__ float Ps[64 * 68];   // [row][col], pad 68

    const int tid = threadIdx.x;
    const int ty  = tid >> 4;     // 0..15 -> rows ty*4..+3
    const int tx  = tid & 15;     // 0..15 -> S cols tx*4..+3, O dims tx*2..+1
    const int qt  = blockIdx.x;   // 0..31
    const int h   = blockIdx.y;
    const int b   = blockIdx.z;
    const int qr0 = qt * 64;

    const size_t base = (size_t)b * T_ * QKVS;

    // Load Q tile transposed into smem
    #pragma unroll
    for (int it = 0; it < 2; it++) {
        int fid = tid + it * 256;
        int r = fid >> 3, d4 = fid & 7;
        const float* p = g_qkv + base + (size_t)(qr0 + r) * QKVS + h * HD + d4 * 4;
        float4 v = *(const float4*)p;
        Qt[(d4 * 4 + 0) * 68 + r] = v.x;
        Qt[(d4 * 4 + 1) * 68 + r] = v.y;
        Qt[(d4 * 4 + 2) * 68 + r] = v.z;
        Qt[(d4 * 4 + 3) * 68 + r] = v.w;
    }

    float m_i[4], l_i[4], o[4][2];
    #pragma unroll
    for (int i = 0; i < 4; i++) {
        m_i[i] = -1e30f; l_i[i] = 0.f; o[i][0] = 0.f; o[i][1] = 0.f;
    }

    const float scale = 0.17677669529663687f;  // 1/sqrt(32)

    for (int kt = 0; kt <= qt; kt++) {
        const int kn0 = kt * 64;
        __syncthreads();  // previous-iteration smem reads complete

        // Load K (transposed) and V tiles
        #pragma unroll
        for (int it = 0; it < 2; it++) {
            int fid = tid + it * 256;
            int c = fid >> 3, d4 = fid & 7;
            const float* p = g_qkv + base + (size_t)(kn0 + c) * QKVS + CE + h * HD + d4 * 4;
            float4 v = *(const float4*)p;
            Kt[(d4 * 4 + 0) * 68 + c] = v.x;
            Kt[(d4 * 4 + 1) * 68 + c] = v.y;
            Kt[(d4 * 4 + 2) * 68 + c] = v.z;
            Kt[(d4 * 4 + 3) * 68 + c] = v.w;
        }
        #pragma unroll
        for (int it = 0; it < 2; it++) {
            int fid = tid + it * 256;
            int c = fid >> 3, d4 = fid & 7;
            const float* p = g_qkv + base + (size_t)(kn0 + c) * QKVS + 2 * CE + h * HD + d4 * 4;
            *(float4*)(Vs + c * 32 + d4 * 4) = *(const float4*)p;
        }
        __syncthreads();

        // S = Q @ K^T (scaled)
        float s[4][4];
        #pragma unroll
        for (int i = 0; i < 4; i++)
            #pragma unroll
            for (int j = 0; j < 4; j++) s[i][j] = 0.f;

        #pragma unroll
        for (int d = 0; d < 32; d++) {
            float4 a  = *(const float4*)(Qt + d * 68 + ty * 4);
            float4 kk = *(const float4*)(Kt + d * 68 + tx * 4);
            float av[4] = {a.x, a.y, a.z, a.w};
            float kv[4] = {kk.x, kk.y, kk.z, kk.w};
            #pragma unroll
            for (int i = 0; i < 4; i++)
                #pragma unroll
                for (int j = 0; j < 4; j++)
                    s[i][j] = fmaf(av[i], kv[j], s[i][j]);
        }

        const bool diag = (kt == qt);
        #pragma unroll
        for (int i = 0; i < 4; i++)
            #pragma unroll
            for (int j = 0; j < 4; j++) {
                float v = s[i][j] * scale;
                if (diag && (kn0 + tx * 4 + j > qr0 + ty * 4 + i)) v = -1e30f;
                s[i][j] = v;
            }

        // Online softmax update (row reductions across the 16-lane tx group)
        #pragma unroll
        for (int i = 0; i < 4; i++) {
            float tmax = fmaxf(fmaxf(s[i][0], s[i][1]), fmaxf(s[i][2], s[i][3]));
            #pragma unroll
            for (int off = 1; off < 16; off <<= 1)
                tmax = fmaxf(tmax, __shfl_xor_sync(0xffffffffu, tmax, off));
            float mn = fmaxf(m_i[i], tmax);
            float alpha = __expf(m_i[i] - mn);
            m_i[i] = mn;
            float rsum = 0.f;
            #pragma unroll
            for (int j = 0; j < 4; j++) {
                float p = __expf(s[i][j] - mn);
                s[i][j] = p;
                rsum += p;
            }
            #pragma unroll
            for (int off = 1; off < 16; off <<= 1)
                rsum += __shfl_xor_sync(0xffffffffu, rsum, off);
            l_i[i] = l_i[i] * alpha + rsum;
            o[i][0] *= alpha;
            o[i][1] *= alpha;
        }

        // Stage P
        #pragma unroll
        for (int i = 0; i < 4; i++) {
            float4 pv = make_float4(s[i][0], s[i][1], s[i][2], s[i][3]);
            *(float4*)(Ps + (ty * 4 + i) * 68 + tx * 4) = pv;
        }
        __syncthreads();

        // O += P @ V
        #pragma unroll 8
        for (int c = 0; c < 64; c++) {
            float2 v = *(const float2*)(Vs + c * 32 + tx * 2);
            #pragma unroll
            for (int i = 0; i < 4; i++) {
                float p = Ps[(ty * 4 + i) * 68 + c];
                o[i][0] = fmaf(p, v.x, o[i][0]);
                o[i][1] = fmaf(p, v.y, o[i][1]);
            }
        }
    }

    // Epilogue: normalize, write y[b, t, h*32 + dim]
    #pragma unroll
    for (int i = 0; i < 4; i++) {
        float inv = 1.f / l_i[i];
        int t = qr0 + ty * 4 + i;
        float* yp = g_y + ((size_t)(b * T_ + t)) * CE + h * HD + tx * 2;
        yp[0] = o[i][0] * inv;
        yp[1] = o[i][1] * inv;
    }
}

// ---------------------------------------------------------------------------
extern "C" void kernel_launch(void* const* d_in, const int* in_sizes, int n_in,
                              void* d_out, int out_size)
{
    const float* x      = (const float*)d_in[0];
    const float* w_qkv  = (const float*)d_in[1];
    const float* b_qkv  = (const float*)d_in[2];
    const float* w_proj = (const float*)d_in[3];
    const float* b_proj = (const float*)d_in[4];
    float* out = (float*)d_out;

    const int M = B_ * T_;  // 16384

    // 1) qkv = x @ w_qkv + b_qkv  -> g_qkv
    gemm_bias_kernel<0><<<dim3(M / 64, QKVS / 128), 256>>>(
        x, w_qkv, b_qkv, nullptr, M, QKVS, CE);

    // 2) attention -> g_y
    attn_kernel<<<dim3(T_ / 64, NH, B_), 256>>>();

    // 3) out = g_y @ w_proj + b_proj
    gemm_bias_kernel<1><<<dim3(M / 64, CE / 128), 256>>>(
        nullptr, w_proj, b_proj, out, M, CE, CE);
}

// round 5
// speedup vs baseline: 2.9512x; 2.9512x over previous
#include <cuda_runtime.h>
#include <cuda_bf16.h>
#include <cstdint>

#define B_  8
#define T_  2048
#define NH  4
#define HD  32
#define CE  128
#define QKVS 384

// Scratch (device globals: allocation-free, graph-capturable)
__device__ float g_qkv[(size_t)B_ * T_ * QKVS];  // [B,T,384]
__device__ float g_y[(size_t)B_ * T_ * CE];      // [B,T,128]

// ---------------------------------------------------------------------------
// helpers
// ---------------------------------------------------------------------------
__device__ __forceinline__ uint32_t smem_u32(const void* p) {
    return (uint32_t)__cvta_generic_to_shared(p);
}
__device__ __forceinline__ void ldmx4(uint32_t& r0, uint32_t& r1, uint32_t& r2,
                                      uint32_t& r3, uint32_t addr) {
    asm volatile("ldmatrix.sync.aligned.m8n8.x4.shared.b16 {%0,%1,%2,%3}, [%4];"
                 : "=r"(r0), "=r"(r1), "=r"(r2), "=r"(r3) : "r"(addr));
}
__device__ __forceinline__ void ldmx4t(uint32_t& r0, uint32_t& r1, uint32_t& r2,
                                       uint32_t& r3, uint32_t addr) {
    asm volatile("ldmatrix.sync.aligned.m8n8.x4.trans.shared.b16 {%0,%1,%2,%3}, [%4];"
                 : "=r"(r0), "=r"(r1), "=r"(r2), "=r"(r3) : "r"(addr));
}
__device__ __forceinline__ void mma16816(float (&c)[4], const uint32_t (&a)[4],
                                         uint32_t b0, uint32_t b1) {
    asm volatile(
        "mma.sync.aligned.m16n8k16.row.col.f32.bf16.bf16.f32 "
        "{%0,%1,%2,%3}, {%4,%5,%6,%7}, {%8,%9}, {%0,%1,%2,%3};"
        : "+f"(c[0]), "+f"(c[1]), "+f"(c[2]), "+f"(c[3])
        : "r"(a[0]), "r"(a[1]), "r"(a[2]), "r"(a[3]), "r"(b0), "r"(b1));
}
__device__ __forceinline__ float ex2f(float x) {
    float r; asm("ex2.approx.f32 %0, %1;" : "=f"(r) : "f"(x)); return r;
}
__device__ __forceinline__ uint32_t packbf(float a, float b) {
    __nv_bfloat162 t = __floats2bfloat162_rn(a, b);
    return *reinterpret_cast<uint32_t*>(&t);
}
// store (a,b) split into hi/lo bf16 pairs
__device__ __forceinline__ void split2pack(float a, float b,
                                           __nv_bfloat16* ph, __nv_bfloat16* pl) {
    __nv_bfloat162 hi = __floats2bfloat162_rn(a, b);
    *reinterpret_cast<__nv_bfloat162*>(ph) = hi;
    float ra = a - __bfloat162float(__low2bfloat16(hi));
    float rb = b - __bfloat162float(__high2bfloat16(hi));
    *reinterpret_cast<__nv_bfloat162*>(pl) = __floats2bfloat162_rn(ra, rb);
}
__device__ __forceinline__ float bfres(float a) {
    return a - __bfloat162float(__float2bfloat16(a));
}

// ---------------------------------------------------------------------------
// GEMM + bias via mma (hi/lo split): C[M,N] = A[M,128] @ W[128,N] + bias
// 256 threads (8 warps), BM=128 (16-row warp strips), BN=64, BK=32 x 4 chunks.
// MODE 0: A = param (x),  C = g_qkv     MODE 1: A = g_y, C = param (out)
// ---------------------------------------------------------------------------
template <int MODE>
__global__ __launch_bounds__(256) void gemm_mma(
    const float* __restrict__ Ap, const float* __restrict__ W,
    const float* __restrict__ bias, float* __restrict__ Cp, int N)
{
    const float* A = (MODE == 0) ? Ap : g_y;
    float*       C = (MODE == 0) ? g_qkv : Cp;
    const int K = CE;

    __shared__ __nv_bfloat16 Ah[128 * 40], Al[128 * 40];  // [row][k] pad 40
    __shared__ __nv_bfloat16 Wh[32 * 72],  Wl[32 * 72];   // [k][n]  pad 72

    const int tid = threadIdx.x;
    const int w   = tid >> 5;
    const int l   = tid & 31;
    const int bm0 = blockIdx.x * 128;
    const int bn0 = blockIdx.y * 64;

    float acc[8][4];
    #pragma unroll
    for (int i = 0; i < 8; i++)
        #pragma unroll
        for (int j = 0; j < 4; j++) acc[i][j] = 0.f;

    for (int k0 = 0; k0 < 128; k0 += 32) {
        if (k0) __syncthreads();
        // A chunk 128x32: 1024 float4
        #pragma unroll
        for (int it = 0; it < 4; it++) {
            int fid = tid + it * 256;
            int r = fid >> 3, c4 = (fid & 7) << 2;
            float4 v = *(const float4*)(A + (size_t)(bm0 + r) * K + k0 + c4);
            split2pack(v.x, v.y, &Ah[r * 40 + c4],     &Al[r * 40 + c4]);
            split2pack(v.z, v.w, &Ah[r * 40 + c4 + 2], &Al[r * 40 + c4 + 2]);
        }
        // W chunk 32x64: 512 float4
        #pragma unroll
        for (int it = 0; it < 2; it++) {
            int fid = tid + it * 256;
            int r = fid >> 4, c4 = (fid & 15) << 2;
            float4 v = *(const float4*)(W + (size_t)(k0 + r) * N + bn0 + c4);
            split2pack(v.x, v.y, &Wh[r * 72 + c4],     &Wl[r * 72 + c4]);
            split2pack(v.z, v.w, &Wh[r * 72 + c4 + 2], &Wl[r * 72 + c4 + 2]);
        }
        __syncthreads();

        uint32_t ahf[2][4], alf[2][4];
        #pragma unroll
        for (int ks2 = 0; ks2 < 2; ks2++) {
            int off = (w * 16 + (l & 7) + ((l >> 3) & 1) * 8) * 40
                      + ks2 * 16 + ((l >> 4) & 1) * 8;
            ldmx4(ahf[ks2][0], ahf[ks2][1], ahf[ks2][2], ahf[ks2][3], smem_u32(&Ah[off]));
            ldmx4(alf[ks2][0], alf[ks2][1], alf[ks2][2], alf[ks2][3], smem_u32(&Al[off]));
        }
        #pragma unroll
        for (int ks2 = 0; ks2 < 2; ks2++) {
            #pragma unroll
            for (int np = 0; np < 4; np++) {
                int off = (ks2 * 16 + ((l >> 3) & 1) * 8 + (l & 7)) * 72
                          + np * 16 + ((l >> 4) & 1) * 8;
                uint32_t wh0, wh1, wh2, wh3, wl0, wl1, wl2, wl3;
                ldmx4t(wh0, wh1, wh2, wh3, smem_u32(&Wh[off]));
                ldmx4t(wl0, wl1, wl2, wl3, smem_u32(&Wl[off]));
                mma16816(acc[2 * np],     ahf[ks2], wh0, wh1);
                mma16816(acc[2 * np],     ahf[ks2], wl0, wl1);
                mma16816(acc[2 * np],     alf[ks2], wh0, wh1);
                mma16816(acc[2 * np + 1], ahf[ks2], wh2, wh3);
                mma16816(acc[2 * np + 1], ahf[ks2], wl2, wl3);
                mma16816(acc[2 * np + 1], alf[ks2], wh2, wh3);
            }
        }
    }

    const int g = l >> 2, j2 = (l & 3) * 2;
    #pragma unroll
    for (int nt = 0; nt < 8; nt++) {
        int n = bn0 + nt * 8 + j2;
        float b0 = bias[n], b1 = bias[n + 1];
        float* p0 = C + (size_t)(bm0 + w * 16 + g) * N + n;
        float* p1 = C + (size_t)(bm0 + w * 16 + 8 + g) * N + n;
        *(float2*)p0 = make_float2(acc[nt][0] + b0, acc[nt][1] + b1);
        *(float2*)p1 = make_float2(acc[nt][2] + b0, acc[nt][3] + b1);
    }
}

// ---------------------------------------------------------------------------
// Flash attention via mma (hi/lo split). 128 threads (4 warps).
// Q tile 64 (16 rows/warp), KV tile 64, D=32. FA2 register layout:
// S C-fragments feed PV A-fragments directly, softmax = 2 shfls per row.
// ---------------------------------------------------------------------------
__global__ __launch_bounds__(128) void attn_mma()
{
    __shared__ __nv_bfloat16 Qh[64 * 40], Ql[64 * 40];
    __shared__ __nv_bfloat16 Kh[64 * 40], Kl[64 * 40];
    __shared__ __nv_bfloat16 Vh[64 * 40], Vl[64 * 40];

    const int tid = threadIdx.x;
    const int w   = tid >> 5;
    const int l   = tid & 31;
    const int qt  = gridDim.x - 1 - blockIdx.x;   // heavy tiles first
    const int hh  = blockIdx.y;
    const int b   = blockIdx.z;
    const int qr0 = qt * 64;
    const size_t base = (size_t)b * T_ * QKVS;
    const float sc2 = 0.17677669529663687f * 1.4426950408889634f; // 1/sqrt(32)*log2e

    // Load Q (scaled) hi/lo into smem
    #pragma unroll
    for (int it = 0; it < 4; it++) {
        int fid = tid + it * 128;
        int r = fid >> 3, c4 = (fid & 7) << 2;
        float4 v = *(const float4*)(g_qkv + base + (size_t)(qr0 + r) * QKVS + hh * HD + c4);
        split2pack(v.x * sc2, v.y * sc2, &Qh[r * 40 + c4],     &Ql[r * 40 + c4]);
        split2pack(v.z * sc2, v.w * sc2, &Qh[r * 40 + c4 + 2], &Ql[r * 40 + c4 + 2]);
    }
    __syncthreads();

    // Q fragments persist in registers (2 k-steps x hi/lo)
    uint32_t qh[2][4], ql[2][4];
    #pragma unroll
    for (int ks2 = 0; ks2 < 2; ks2++) {
        int off = (w * 16 + (l & 7) + ((l >> 3) & 1) * 8) * 40
                  + ks2 * 16 + ((l >> 4) & 1) * 8;
        ldmx4(qh[ks2][0], qh[ks2][1], qh[ks2][2], qh[ks2][3], smem_u32(&Qh[off]));
        ldmx4(ql[ks2][0], ql[ks2][1], ql[ks2][2], ql[ks2][3], smem_u32(&Ql[off]));
    }

    float m2[2] = {-1e30f, -1e30f}, li[2] = {0.f, 0.f};
    float o[4][4];
    #pragma unroll
    for (int i = 0; i < 4; i++)
        #pragma unroll
        for (int j = 0; j < 4; j++) o[i][j] = 0.f;

    const int row0 = qr0 + w * 16 + (l >> 2);
    const int row1 = row0 + 8;

    for (int kt = 0; kt <= qt; kt++) {
        const int kn0 = kt * 64;
        __syncthreads();
        // Load K & V hi/lo
        #pragma unroll
        for (int it = 0; it < 4; it++) {
            int fid = tid + it * 128;
            int r = fid >> 3, c4 = (fid & 7) << 2;
            const float* kp = g_qkv + base + (size_t)(kn0 + r) * QKVS + CE + hh * HD + c4;
            float4 kv = *(const float4*)kp;
            split2pack(kv.x, kv.y, &Kh[r * 40 + c4],     &Kl[r * 40 + c4]);
            split2pack(kv.z, kv.w, &Kh[r * 40 + c4 + 2], &Kl[r * 40 + c4 + 2]);
            const float* vp = kp + CE;
            float4 vv = *(const float4*)vp;
            split2pack(vv.x, vv.y, &Vh[r * 40 + c4],     &Vl[r * 40 + c4]);
            split2pack(vv.z, vv.w, &Vh[r * 40 + c4 + 2], &Vl[r * 40 + c4 + 2]);
        }
        __syncthreads();

        // ---- S = Q @ K^T (in log2 units; scale folded into Q) ----
        float s[8][4];
        #pragma unroll
        for (int i = 0; i < 8; i++)
            #pragma unroll
            for (int j = 0; j < 4; j++) s[i][j] = 0.f;

        #pragma unroll
        for (int ks2 = 0; ks2 < 2; ks2++) {
            #pragma unroll
            for (int np = 0; np < 4; np++) {
                int off = (np * 16 + ((l >> 4) & 1) * 8 + (l & 7)) * 40
                          + ks2 * 16 + ((l >> 3) & 1) * 8;
                uint32_t kh0, kh1, kh2, kh3, kl0, kl1, kl2, kl3;
                ldmx4(kh0, kh1, kh2, kh3, smem_u32(&Kh[off]));
                ldmx4(kl0, kl1, kl2, kl3, smem_u32(&Kl[off]));
                mma16816(s[2 * np],     qh[ks2], kh0, kh1);
                mma16816(s[2 * np],     qh[ks2], kl0, kl1);
                mma16816(s[2 * np],     ql[ks2], kh0, kh1);
                mma16816(s[2 * np + 1], qh[ks2], kh2, kh3);
                mma16816(s[2 * np + 1], qh[ks2], kl2, kl3);
                mma16816(s[2 * np + 1], ql[ks2], kh2, kh3);
            }
        }

        // ---- causal mask (diagonal tile only) ----
        if (kt == qt) {
            #pragma unroll
            for (int nt = 0; nt < 8; nt++) {
                int c = kn0 + nt * 8 + (l & 3) * 2;
                if (c > row0)     s[nt][0] = -1e30f;
                if (c + 1 > row0) s[nt][1] = -1e30f;
                if (c > row1)     s[nt][2] = -1e30f;
                if (c + 1 > row1) s[nt][3] = -1e30f;
            }
        }

        // ---- online softmax (base 2) ----
        float mx0 = -1e30f, mx1 = -1e30f;
        #pragma unroll
        for (int nt = 0; nt < 8; nt++) {
            mx0 = fmaxf(mx0, fmaxf(s[nt][0], s[nt][1]));
            mx1 = fmaxf(mx1, fmaxf(s[nt][2], s[nt][3]));
        }
        mx0 = fmaxf(mx0, __shfl_xor_sync(0xffffffffu, mx0, 1));
        mx0 = fmaxf(mx0, __shfl_xor_sync(0xffffffffu, mx0, 2));
        mx1 = fmaxf(mx1, __shfl_xor_sync(0xffffffffu, mx1, 1));
        mx1 = fmaxf(mx1, __shfl_xor_sync(0xffffffffu, mx1, 2));
        float mn0 = fmaxf(m2[0], mx0), mn1 = fmaxf(m2[1], mx1);
        float al0 = ex2f(m2[0] - mn0), al1 = ex2f(m2[1] - mn1);
        m2[0] = mn0; m2[1] = mn1;
        float rs0 = 0.f, rs1 = 0.f;
        #pragma unroll
        for (int nt = 0; nt < 8; nt++) {
            s[nt][0] = ex2f(s[nt][0] - mn0);
            s[nt][1] = ex2f(s[nt][1] - mn0);
            s[nt][2] = ex2f(s[nt][2] - mn1);
            s[nt][3] = ex2f(s[nt][3] - mn1);
            rs0 += s[nt][0] + s[nt][1];
            rs1 += s[nt][2] + s[nt][3];
        }
        rs0 += __shfl_xor_sync(0xffffffffu, rs0, 1);
        rs0 += __shfl_xor_sync(0xffffffffu, rs0, 2);
        rs1 += __shfl_xor_sync(0xffffffffu, rs1, 1);
        rs1 += __shfl_xor_sync(0xffffffffu, rs1, 2);
        li[0] = li[0] * al0 + rs0;
        li[1] = li[1] * al1 + rs1;
        #pragma unroll
        for (int nt = 0; nt < 4; nt++) {
            o[nt][0] *= al0; o[nt][1] *= al0;
            o[nt][2] *= al1; o[nt][3] *= al1;
        }

        // ---- O += P @ V (P from registers, hi/lo split) ----
        #pragma unroll
        for (int kk = 0; kk < 4; kk++) {
            uint32_t ah[4], alr[4];
            ah[0]  = packbf(s[2 * kk][0], s[2 * kk][1]);
            ah[1]  = packbf(s[2 * kk][2], s[2 * kk][3]);
            ah[2]  = packbf(s[2 * kk + 1][0], s[2 * kk + 1][1]);
            ah[3]  = packbf(s[2 * kk + 1][2], s[2 * kk + 1][3]);
            alr[0] = packbf(bfres(s[2 * kk][0]), bfres(s[2 * kk][1]));
            alr[1] = packbf(bfres(s[2 * kk][2]), bfres(s[2 * kk][3]));
            alr[2] = packbf(bfres(s[2 * kk + 1][0]), bfres(s[2 * kk + 1][1]));
            alr[3] = packbf(bfres(s[2 * kk + 1][2]), bfres(s[2 * kk + 1][3]));
            #pragma unroll
            for (int np = 0; np < 2; np++) {
                int off = (kk * 16 + ((l >> 3) & 1) * 8 + (l & 7)) * 40
                          + np * 16 + ((l >> 4) & 1) * 8;
                uint32_t vh0, vh1, vh2, vh3, vl0, vl1, vl2, vl3;
                ldmx4t(vh0, vh1, vh2, vh3, smem_u32(&Vh[off]));
                ldmx4t(vl0, vl1, vl2, vl3, smem_u32(&Vl[off]));
                mma16816(o[2 * np],     ah,  vh0, vh1);
                mma16816(o[2 * np],     ah,  vl0, vl1);
                mma16816(o[2 * np],     alr, vh0, vh1);
                mma16816(o[2 * np + 1], ah,  vh2, vh3);
                mma16816(o[2 * np + 1], ah,  vl2, vl3);
                mma16816(o[2 * np + 1], alr, vh2, vh3);
            }
        }
    }

    // ---- epilogue ----
    float inv0 = 1.f / li[0], inv1 = 1.f / li[1];
    size_t yb0 = ((size_t)b * T_ + row0) * CE + hh * HD;
    size_t yb1 = yb0 + (size_t)8 * CE;
    #pragma unroll
    for (int nt = 0; nt < 4; nt++) {
        int d = nt * 8 + (l & 3) * 2;
        *(float2*)(g_y + yb0 + d) = make_float2(o[nt][0] * inv0, o[nt][1] * inv0);
        *(float2*)(g_y + yb1 + d) = make_float2(o[nt][2] * inv1, o[nt][3] * inv1);
    }
}

// ---------------------------------------------------------------------------
extern "C" void kernel_launch(void* const* d_in, const int* in_sizes, int n_in,
                              void* d_out, int out_size)
{
    const float* x      = (const float*)d_in[0];
    const float* w_qkv  = (const float*)d_in[1];
    const float* b_qkv  = (const float*)d_in[2];
    const float* w_proj = (const float*)d_in[3];
    const float* b_proj = (const float*)d_in[4];
    float* out = (float*)d_out;

    // 1) qkv = x @ w_qkv + b_qkv  -> g_qkv
    gemm_mma<0><<<dim3(128, 6), 256>>>(x, w_qkv, b_qkv, nullptr, QKVS);

    // 2) attention -> g_y
    attn_mma<<<dim3(T_ / 64, NH, B_), 128>>>();

    // 3) out = g_y @ w_proj + b_proj
    gemm_mma<1><<<dim3(128, 2), 256>>>(nullptr, w_proj, b_proj, out, CE);
}